// round 2
// baseline (speedup 1.0000x reference)
#include <cuda_runtime.h>
#include <math_constants.h>

// Problem constants (ProbAttention: B=4, L=4096, H=8, D=64, FACTOR=5)
#define B_ 4
#define L_ 4096
#define H_ 8
#define D_ 64
#define SK_ 45   // sample_k = min(5*ceil(ln(4096)), 4096) = 45
#define U_  45   // u (top-k count), same formula

// Scratch (static device globals — no allocation allowed)
__device__ float g_M[B_ * H_ * L_];        // sparsity scores M[b,h,l]
__device__ int   g_Mtop[B_ * H_ * U_];     // top-u query indices per (b,h)
__device__ float g_vmean[B_ * H_ * D_];    // sum over L of V (divided at use)

// ---------------------------------------------------------------------------
// Kernel 1: M[b,h,l] = max_s(Q[b,h,l]·K[b,h,idx[l,s]]) - (1/L)*sum_s(...)
// One warp per (b,h,l). Lane holds 2 of the 64 dims.
// NOTE: index_sample is int32 (JAX x64 disabled -> jnp.int64 silently int32).
// ---------------------------------------------------------------------------
__global__ void kernel_M(const float* __restrict__ Q,
                         const float* __restrict__ K,
                         const int* __restrict__ idx) {
    int w = (blockIdx.x * blockDim.x + threadIdx.x) >> 5;   // [0, B*H*L)
    int lane = threadIdx.x & 31;
    int l = w & (L_ - 1);
    int h = (w >> 12) & (H_ - 1);
    int b = w >> 15;

    const float* qrow = Q + ((b * L_ + l) * H_ + h) * D_;
    float q0 = qrow[lane];
    float q1 = qrow[lane + 32];

    float mx = -CUDART_INF_F;
    float sm = 0.0f;
    const int* ip = idx + l * SK_;
#pragma unroll 5
    for (int s = 0; s < SK_; s++) {
        int kr = ip[s];
        const float* krow = K + ((b * L_ + kr) * H_ + h) * D_;
        float d = q0 * __ldg(krow + lane) + q1 * __ldg(krow + lane + 32);
#pragma unroll
        for (int off = 16; off; off >>= 1) d += __shfl_xor_sync(0xFFFFFFFFu, d, off);
        mx = fmaxf(mx, d);
        sm += d;
    }
    if (lane == 0) g_M[w] = mx - sm * (1.0f / (float)L_);
}

// ---------------------------------------------------------------------------
// Kernel 2: top-U per (b,h) via iterative argmax in smem. 32 blocks.
// (Index ORDER within top-k is irrelevant: final scatter is a set update.)
// ---------------------------------------------------------------------------
__global__ void kernel_topk() {
    __shared__ float sM[L_];
    __shared__ float smax[256];
    __shared__ int   sidx[256];
    int bh = blockIdx.x;
    int t = threadIdx.x;
    const float* m = g_M + bh * L_;
    for (int i = t; i < L_; i += 256) sM[i] = m[i];
    __syncthreads();
    for (int it = 0; it < U_; it++) {
        float best = -CUDART_INF_F;
        int bi = -1;
        for (int i = t; i < L_; i += 256) {
            float v = sM[i];
            if (v > best) { best = v; bi = i; }
        }
        smax[t] = best; sidx[t] = bi;
        __syncthreads();
        for (int s = 128; s; s >>= 1) {
            if (t < s && smax[t + s] > smax[t]) { smax[t] = smax[t + s]; sidx[t] = sidx[t + s]; }
            __syncthreads();
        }
        if (t == 0) {
            g_Mtop[bh * U_ + it] = sidx[0];
            sM[sidx[0]] = -CUDART_INF_F;
        }
        __syncthreads();
    }
}

// ---------------------------------------------------------------------------
// Kernel 3a: zero the V-mean accumulator
// ---------------------------------------------------------------------------
__global__ void kernel_zero_mean() {
    int i = blockIdx.x * blockDim.x + threadIdx.x;
    if (i < B_ * H_ * D_) g_vmean[i] = 0.0f;
}

// ---------------------------------------------------------------------------
// Kernel 3b: partial sums of V over L.  grid = B*H*8 blocks, 256 thr.
// block covers 512 consecutive l.  thread: d = t&63, sub = t>>6.
// ---------------------------------------------------------------------------
__global__ void kernel_mean_part(const float* __restrict__ V) {
    int blk = blockIdx.x;
    int seg = blk & 7;
    int bh = blk >> 3;
    int h = bh & (H_ - 1);
    int b = bh >> 3;
    int t = threadIdx.x;
    int d = t & 63;
    int sub = t >> 6;                 // 0..3
    int l0 = seg * 512;
    float acc = 0.0f;
    for (int l = l0 + sub; l < l0 + 512; l += 4)
        acc += V[((b * L_ + l) * H_ + h) * D_ + d];
    __shared__ float s[4][64];
    s[sub][d] = acc;
    __syncthreads();
    if (t < 64)
        atomicAdd(&g_vmean[bh * D_ + t], s[0][t] + s[1][t] + s[2][t] + s[3][t]);
}

// ---------------------------------------------------------------------------
// Kernel 4: fill out[b,l,h,d] = vmean_sum[b,h,d] / L   (fully coalesced)
// ---------------------------------------------------------------------------
__global__ void kernel_fill(float* __restrict__ out) {
    unsigned i = blockIdx.x * blockDim.x + threadIdx.x;  // < B*L*H*D = 8.4M
    int d = i & 63;
    int h = (i >> 6) & 7;
    int b = i >> 21;                  // i / (L*H*D) with L*H*D = 2^21
    out[i] = g_vmean[(b * H_ + h) * D_ + d] * (1.0f / (float)L_);
}

// ---------------------------------------------------------------------------
// Kernel 5: full attention row for each selected query.
// grid = B*H*U blocks, 256 threads.
// Pass 1: scores into smem + online max; Pass 2: softmax; Pass 3: attn @ V.
// ---------------------------------------------------------------------------
__global__ void kernel_attn(const float* __restrict__ Q,
                            const float* __restrict__ K,
                            const float* __restrict__ V,
                            float* __restrict__ out) {
    __shared__ float sq[D_];
    __shared__ float sc[L_];
    __shared__ float red[256];
    __shared__ float accs[4][D_];

    int u = blockIdx.x % U_;
    int bh = blockIdx.x / U_;
    int h = bh & (H_ - 1);
    int b = bh >> 3;
    int t = threadIdx.x;
    int lsel = g_Mtop[bh * U_ + u];

    if (t < D_) sq[t] = Q[((b * L_ + lsel) * H_ + h) * D_ + t];
    __syncthreads();

    const float scale = 0.125f;  // 1/sqrt(64)
    float lmax = -CUDART_INF_F;
    for (int k = t; k < L_; k += 256) {
        const float* krow = K + ((b * L_ + k) * H_ + h) * D_;
        float dot = 0.0f;
#pragma unroll
        for (int d = 0; d < D_; d += 4) {
            float4 kv = *(const float4*)(krow + d);
            dot += kv.x * sq[d] + kv.y * sq[d + 1] + kv.z * sq[d + 2] + kv.w * sq[d + 3];
        }
        dot *= scale;
        sc[k] = dot;
        lmax = fmaxf(lmax, dot);
    }
    red[t] = lmax;
    __syncthreads();
    for (int s = 128; s; s >>= 1) { if (t < s) red[t] = fmaxf(red[t], red[t + s]); __syncthreads(); }
    float gmax = red[0];
    __syncthreads();

    float lsum = 0.0f;
    for (int k = t; k < L_; k += 256) {
        float e = __expf(sc[k] - gmax);
        sc[k] = e;
        lsum += e;
    }
    red[t] = lsum;
    __syncthreads();
    for (int s = 128; s; s >>= 1) { if (t < s) red[t] += red[t + s]; __syncthreads(); }
    float inv = 1.0f / red[0];
    __syncthreads();

    // Pass 3: out[d] = (1/sum) * sum_k sc[k] * V[b,k,h,d]
    int d = t & 63;
    int sub = t >> 6;  // 0..3
    float acc = 0.0f;
    for (int k = sub; k < L_; k += 4)
        acc += sc[k] * V[((b * L_ + k) * H_ + h) * D_ + d];
    accs[sub][d] = acc;
    __syncthreads();
    if (t < D_) {
        float tot = (accs[0][t] + accs[1][t] + accs[2][t] + accs[3][t]) * inv;
        out[((b * L_ + lsel) * H_ + h) * D_ + t] = tot;
    }
}

// ---------------------------------------------------------------------------
extern "C" void kernel_launch(void* const* d_in, const int* in_sizes, int n_in,
                              void* d_out, int out_size) {
    const float* Q = (const float*)d_in[0];
    const float* K = (const float*)d_in[1];
    const float* V = (const float*)d_in[2];
    const int* idx = (const int*)d_in[3];   // int32! (JAX default x64-disabled)
    float* out = (float*)d_out;

    // 1. M scores: one warp per (b,h,l) -> B*H*L warps
    kernel_M<<<(B_ * H_ * L_) / 8, 256>>>(Q, K, idx);
    // 2. top-k per (b,h)
    kernel_topk<<<B_ * H_, 256>>>();
    // 3. V mean
    kernel_zero_mean<<<(B_ * H_ * D_ + 255) / 256, 256>>>();
    kernel_mean_part<<<B_ * H_ * 8, 256>>>(V);
    // 4. broadcast fill of output
    kernel_fill<<<(B_ * L_ * H_ * D_) / 256, 256>>>(out);
    // 5. dense attention for the u selected rows per (b,h)
    kernel_attn<<<B_ * H_ * U_, 256>>>(Q, K, V, out);
}

// round 3
// speedup vs baseline: 1.8379x; 1.8379x over previous
#include <cuda_runtime.h>
#include <math_constants.h>

// ProbAttention: B=4, L=4096, H=8, D=64, FACTOR=5
#define B_ 4
#define L_ 4096
#define H_ 8
#define D_ 64
#define SK_ 45
#define U_  45
#define NSPLIT 64
#define KC 64          // keys per split = L_/NSPLIT
#define UPAD 48

// Scratch (device globals; no allocation allowed)
__device__ float g_M[B_ * H_ * L_];
__device__ int   g_Mtop[B_ * H_ * U_];
__device__ float g_vmean[B_ * H_ * D_];
__device__ float g_pm[B_ * H_ * NSPLIT * U_];
__device__ float g_ps[B_ * H_ * NSPLIT * U_];
__device__ float g_pacc[B_ * H_ * NSPLIT * U_ * D_];   // 23.6 MB

// ---------------------------------------------------------------------------
// Kernel 1: M[b,h,l] = max_s(Q·K_s) - (1/L)*sum_s(Q·K_s)
// One warp per (b,h,l); 4 samples in flight (8 lanes per 256B K row).
// ---------------------------------------------------------------------------
__global__ void kernel_M(const float* __restrict__ Q,
                         const float* __restrict__ K,
                         const int* __restrict__ idx) {
    int w = (blockIdx.x * blockDim.x + threadIdx.x) >> 5;   // [0, B*H*L)
    int lane = threadIdx.x & 31;
    int li = lane & 7;        // position within 8-lane row group
    int g  = lane >> 3;       // sample group 0..3
    int l = w & (L_ - 1);
    int h = (w >> 12) & (H_ - 1);
    int b = w >> 15;

    const float4* q4 = (const float4*)(Q + ((b * L_ + l) * H_ + h) * D_);
    float4 qa = q4[li * 2];
    float4 qb = q4[li * 2 + 1];

    const int* ip = idx + l * SK_;
    float mx = -CUDART_INF_F;
    float sm = 0.0f;
#pragma unroll
    for (int sg = 0; sg < 12; sg++) {
        int s = sg * 4 + g;
        bool valid = (s < SK_);
        int kr = ip[valid ? s : 0];
        const float4* k4 = (const float4*)(K + ((b * L_ + kr) * H_ + h) * D_);
        float4 ka = k4[li * 2];
        float4 kb = k4[li * 2 + 1];
        float d = qa.x * ka.x + qa.y * ka.y + qa.z * ka.z + qa.w * ka.w
                + qb.x * kb.x + qb.y * kb.y + qb.z * kb.z + qb.w * kb.w;
        d += __shfl_xor_sync(0xffffffffu, d, 4);
        d += __shfl_xor_sync(0xffffffffu, d, 2);
        d += __shfl_xor_sync(0xffffffffu, d, 1);
        if (valid) { mx = fmaxf(mx, d); sm += d; }
    }
    mx = fmaxf(mx, __shfl_xor_sync(0xffffffffu, mx, 8));
    mx = fmaxf(mx, __shfl_xor_sync(0xffffffffu, mx, 16));
    sm += __shfl_xor_sync(0xffffffffu, sm, 8);
    sm += __shfl_xor_sync(0xffffffffu, sm, 16);
    if (lane == 0) g_M[w] = mx - sm * (1.0f / (float)L_);
}

// ---------------------------------------------------------------------------
// Kernel 2: top-U per (b,h) via iterative argmax in smem.
// ---------------------------------------------------------------------------
__global__ void kernel_topk() {
    __shared__ float sM[L_];
    __shared__ float smax[256];
    __shared__ int   sidx[256];
    int bh = blockIdx.x;
    int t = threadIdx.x;
    const float* m = g_M + bh * L_;
    for (int i = t; i < L_; i += 256) sM[i] = m[i];
    __syncthreads();
    for (int it = 0; it < U_; it++) {
        float best = -CUDART_INF_F;
        int bi = -1;
        for (int i = t; i < L_; i += 256) {
            float v = sM[i];
            if (v > best) { best = v; bi = i; }
        }
        smax[t] = best; sidx[t] = bi;
        __syncthreads();
        for (int s = 128; s; s >>= 1) {
            if (t < s && smax[t + s] > smax[t]) { smax[t] = smax[t + s]; sidx[t] = sidx[t + s]; }
            __syncthreads();
        }
        if (t == 0) {
            g_Mtop[bh * U_ + it] = sidx[0];
            sM[sidx[0]] = -CUDART_INF_F;
        }
        __syncthreads();
    }
}

// ---------------------------------------------------------------------------
// Kernel 3: V mean (zero + partial sums, 32 segments per (b,h))
// ---------------------------------------------------------------------------
__global__ void kernel_zero_mean() {
    int i = blockIdx.x * blockDim.x + threadIdx.x;
    if (i < B_ * H_ * D_) g_vmean[i] = 0.0f;
}

__global__ void kernel_mean_part(const float* __restrict__ V) {
    int blk = blockIdx.x;              // 32*32 blocks
    int seg = blk & 31;
    int bh = blk >> 5;
    int h = bh & (H_ - 1);
    int b = bh >> 3;
    int t = threadIdx.x;
    int d = t & 63;
    int sub = t >> 6;
    int l0 = seg * 128;
    float acc = 0.0f;
    for (int l = l0 + sub; l < l0 + 128; l += 4)
        acc += V[((b * L_ + l) * H_ + h) * D_ + d];
    __shared__ float s[4][64];
    s[sub][d] = acc;
    __syncthreads();
    if (t < 64)
        atomicAdd(&g_vmean[bh * D_ + t], s[0][t] + s[1][t] + s[2][t] + s[3][t]);
}

// ---------------------------------------------------------------------------
// Kernel 4: fill out with V-mean broadcast (coalesced)
// ---------------------------------------------------------------------------
__global__ void kernel_fill(float* __restrict__ out) {
    unsigned i = blockIdx.x * blockDim.x + threadIdx.x;
    int d = i & 63;
    int h = (i >> 6) & 7;
    int b = i >> 21;
    out[i] = g_vmean[(b * H_ + h) * D_ + d] * (1.0f / (float)L_);
}

// ---------------------------------------------------------------------------
// Kernel 5: split-KV flash attention over the 45 selected queries per (b,h).
// grid = 32 (bh) x 64 (splits), 256 threads. Partial (m, s, acc) per split.
// ---------------------------------------------------------------------------
__global__ void __launch_bounds__(256) kernel_attn_part(
        const float* __restrict__ Q,
        const float* __restrict__ K,
        const float* __restrict__ V) {
    __shared__ float sQ[UPAD][D_];     // 12 KB (rows >= U_ zeroed)
    __shared__ float sKV[D_][68];      // 17 KB: K as [k][d-padded], then V^T as [d][k]
    __shared__ float sSC[UPAD][68];    // 13 KB scores -> exp weights
    __shared__ int sMtop[U_];

    int bh = blockIdx.x >> 6;
    int sp = blockIdx.x & 63;
    int h = bh & 7, b = bh >> 3;
    int k0 = sp * KC;
    int t = threadIdx.x;

    if (t < U_) sMtop[t] = g_Mtop[bh * U_ + t];
    __syncthreads();

    // Load selected Q rows (zero-pad to 48)
    for (int i = t; i < UPAD * D_; i += 256) {
        int u = i >> 6, d = i & 63;
        sQ[u][d] = (u < U_) ? Q[((b * L_ + sMtop[u]) * H_ + h) * D_ + d] : 0.0f;
    }
    // Load K chunk [KC][D_]
    for (int i = t; i < KC * D_; i += 256) {
        int k = i >> 6, d = i & 63;
        sKV[k][d] = K[((b * L_ + k0 + k) * H_ + h) * D_ + d];
    }
    __syncthreads();

    // Phase 1: scores.  thread = (k = t&63, u-tile of 12)
    {
        int k = t & 63, uq = t >> 6, u0 = uq * 12;
        float acc[12];
#pragma unroll
        for (int j = 0; j < 12; j++) acc[j] = 0.0f;
#pragma unroll
        for (int d4 = 0; d4 < 16; d4++) {
            float4 kv = *(const float4*)&sKV[k][d4 * 4];
#pragma unroll
            for (int j = 0; j < 12; j++) {
                float4 qv = *(const float4*)&sQ[u0 + j][d4 * 4];
                acc[j] += qv.x * kv.x + qv.y * kv.y + qv.z * kv.z + qv.w * kv.w;
            }
        }
#pragma unroll
        for (int j = 0; j < 12; j++) sSC[u0 + j][k] = acc[j] * 0.125f;
    }
    __syncthreads();

    // Load V chunk TRANSPOSED into sKV[d][k] (phase-1 K no longer needed)
    for (int i = t; i < KC * D_; i += 256) {
        int k = i >> 6, d = i & 63;
        sKV[d][k] = V[((b * L_ + k0 + k) * H_ + h) * D_ + d];
    }

    // Phase 2: per-u local max/expsum over the 64 keys; exp in place
    {
        int wp = t >> 5, lane = t & 31;
        for (int i = 0; i < 6; i++) {
            int u = wp + i * 8;
            if (u < U_) {
                float v0 = sSC[u][lane], v1 = sSC[u][lane + 32];
                float m = fmaxf(v0, v1);
                for (int o = 16; o; o >>= 1) m = fmaxf(m, __shfl_xor_sync(0xffffffffu, m, o));
                float e0 = __expf(v0 - m), e1 = __expf(v1 - m);
                float s = e0 + e1;
                for (int o = 16; o; o >>= 1) s += __shfl_xor_sync(0xffffffffu, s, o);
                sSC[u][lane] = e0;
                sSC[u][lane + 32] = e1;
                if (lane == 0) {
                    g_pm[(bh * NSPLIT + sp) * U_ + u] = m;
                    g_ps[(bh * NSPLIT + sp) * U_ + u] = s;
                }
            }
        }
    }
    __syncthreads();

    // Phase 3: partial AV.  thread = (d = t&63, u-tile of 12)
    {
        int d = t & 63, uq = t >> 6, u0 = uq * 12;
        int nu = (uq == 3) ? 9 : 12;
        float acc[12];
#pragma unroll
        for (int j = 0; j < 12; j++) acc[j] = 0.0f;
#pragma unroll
        for (int k4 = 0; k4 < 16; k4++) {
            float4 v4 = *(const float4*)&sKV[d][k4 * 4];
            for (int j = 0; j < nu; j++) {
                float4 e4 = *(const float4*)&sSC[u0 + j][k4 * 4];
                acc[j] += e4.x * v4.x + e4.y * v4.y + e4.z * v4.z + e4.w * v4.w;
            }
        }
        float* pa = g_pacc + (size_t)(bh * NSPLIT + sp) * U_ * D_;
        for (int j = 0; j < nu; j++) pa[(u0 + j) * D_ + d] = acc[j];
    }
}

// ---------------------------------------------------------------------------
// Kernel 6: combine split partials + scatter into output. grid = 32 (bh).
// ---------------------------------------------------------------------------
__global__ void __launch_bounds__(256) kernel_combine(float* __restrict__ out) {
    __shared__ float sf[U_][NSPLIT];   // 11.5 KB per-split weights
    __shared__ int sMtop[U_];
    int bh = blockIdx.x;
    int h = bh & 7, b = bh >> 3;
    int t = threadIdx.x;
    if (t < U_) sMtop[t] = g_Mtop[bh * U_ + t];
    {
        int wp = t >> 5, lane = t & 31;
        for (int i = 0; i < 6; i++) {
            int u = wp + i * 8;
            if (u < U_) {
                float m0 = g_pm[(bh * NSPLIT + lane) * U_ + u];
                float m1 = g_pm[(bh * NSPLIT + lane + 32) * U_ + u];
                float m = fmaxf(m0, m1);
                for (int o = 16; o; o >>= 1) m = fmaxf(m, __shfl_xor_sync(0xffffffffu, m, o));
                float e0 = __expf(m0 - m), e1 = __expf(m1 - m);
                float s = e0 * g_ps[(bh * NSPLIT + lane) * U_ + u]
                        + e1 * g_ps[(bh * NSPLIT + lane + 32) * U_ + u];
                for (int o = 16; o; o >>= 1) s += __shfl_xor_sync(0xffffffffu, s, o);
                float inv = 1.0f / s;
                sf[u][lane] = e0 * inv;
                sf[u][lane + 32] = e1 * inv;
            }
        }
    }
    __syncthreads();
    int d = t & 63, ug = t >> 6;
    for (int u = ug; u < U_; u += 4) {
        float acc = 0.0f;
        const float* pa = g_pacc + (size_t)bh * NSPLIT * U_ * D_ + u * D_ + d;
#pragma unroll 8
        for (int sp = 0; sp < NSPLIT; sp++)
            acc += pa[(size_t)sp * U_ * D_] * sf[u][sp];
        out[((b * L_ + sMtop[u]) * H_ + h) * D_ + d] = acc;
    }
}

// ---------------------------------------------------------------------------
extern "C" void kernel_launch(void* const* d_in, const int* in_sizes, int n_in,
                              void* d_out, int out_size) {
    const float* Q = (const float*)d_in[0];
    const float* K = (const float*)d_in[1];
    const float* V = (const float*)d_in[2];
    const int* idx = (const int*)d_in[3];   // int32 (JAX x64 disabled)
    float* out = (float*)d_out;

    kernel_M<<<(B_ * H_ * L_) / 8, 256>>>(Q, K, idx);
    kernel_topk<<<B_ * H_, 256>>>();
    kernel_zero_mean<<<(B_ * H_ * D_ + 255) / 256, 256>>>();
    kernel_mean_part<<<B_ * H_ * 32, 256>>>(V);
    kernel_fill<<<(B_ * L_ * H_ * D_) / 256, 256>>>(out);
    kernel_attn_part<<<B_ * H_ * NSPLIT, 256>>>(Q, K, V);
    kernel_combine<<<B_ * H_, 256>>>(out);
}

// round 4
// speedup vs baseline: 2.0793x; 1.1314x over previous
#include <cuda_runtime.h>
#include <math_constants.h>

// ProbAttention: B=4, L=4096, H=8, D=64, FACTOR=5
#define B_ 4
#define L_ 4096
#define H_ 8
#define D_ 64
#define SK_ 45
#define U_  45
#define NSPLIT 64
#define KC 64          // keys per split = L_/NSPLIT
#define UPAD 48

// Scratch (device globals; no allocation allowed)
__device__ float g_M[B_ * H_ * L_];
__device__ int   g_Mtop[B_ * H_ * U_];
__device__ float g_vmean[B_ * H_ * D_];
__device__ float g_pm[B_ * H_ * NSPLIT * U_];
__device__ float g_ps[B_ * H_ * NSPLIT * U_];
__device__ float g_pacc[B_ * H_ * NSPLIT * U_ * D_];   // 23.6 MB

// ---------------------------------------------------------------------------
// Kernel 1: M[b,h,l] = max_s(Q·K_s) - (1/L)*sum_s(Q·K_s)
// One warp per (b,h,l); 4 samples in flight (8 lanes per 256B K row).
// Block remap keeps an SM inside one (b,h) K-slice across waves (L1 reuse).
// ---------------------------------------------------------------------------
__global__ void __launch_bounds__(256) kernel_M(const float* __restrict__ Q,
                                                const float* __restrict__ K,
                                                const int* __restrict__ idx) {
    int j = (blockIdx.x * 111) & 16383;      // bijective remap (gcd(111,16384)=1)
    int w = j * 8 + (threadIdx.x >> 5);      // [0, B*H*L)
    int lane = threadIdx.x & 31;
    int li = lane & 7;        // position within 8-lane row group
    int g  = lane >> 3;       // sample group 0..3
    int l = w & (L_ - 1);
    int h = (w >> 12) & (H_ - 1);
    int b = w >> 15;

    const float4* q4 = (const float4*)(Q + ((b * L_ + l) * H_ + h) * D_);
    float4 qa = q4[li * 2];
    float4 qb = q4[li * 2 + 1];

    const int* ip = idx + l * SK_;
    float mx = -CUDART_INF_F;
    float sm = 0.0f;
#pragma unroll
    for (int sg = 0; sg < 12; sg++) {
        int s = sg * 4 + g;
        bool valid = (s < SK_);
        int kr = ip[valid ? s : 0];
        const float4* k4 = (const float4*)(K + ((b * L_ + kr) * H_ + h) * D_);
        float4 ka = k4[li * 2];
        float4 kb = k4[li * 2 + 1];
        float d = qa.x * ka.x + qa.y * ka.y + qa.z * ka.z + qa.w * ka.w
                + qb.x * kb.x + qb.y * kb.y + qb.z * kb.z + qb.w * kb.w;
        d += __shfl_xor_sync(0xffffffffu, d, 4);
        d += __shfl_xor_sync(0xffffffffu, d, 2);
        d += __shfl_xor_sync(0xffffffffu, d, 1);
        if (valid) { mx = fmaxf(mx, d); sm += d; }
    }
    mx = fmaxf(mx, __shfl_xor_sync(0xffffffffu, mx, 8));
    mx = fmaxf(mx, __shfl_xor_sync(0xffffffffu, mx, 16));
    sm += __shfl_xor_sync(0xffffffffu, sm, 8);
    sm += __shfl_xor_sync(0xffffffffu, sm, 16);
    if (lane == 0) g_M[w] = mx - sm * (1.0f / (float)L_);
}

// ---------------------------------------------------------------------------
// Kernel 2: top-U per (b,h) via two-level radix histogram + exact tail select.
// ---------------------------------------------------------------------------
__device__ __forceinline__ unsigned f2key(float f) {
    unsigned u = __float_as_uint(f);
    return (u & 0x80000000u) ? ~u : (u | 0x80000000u);
}

__global__ void __launch_bounds__(256) kernel_topk() {
    __shared__ unsigned skeys[L_];        // 16 KB
    __shared__ int hist[256];
    __shared__ unsigned candKey[1024];
    __shared__ int candIdx[1024];
    __shared__ int sT1, sN1, sT2;
    __shared__ int cSel, cCand;
    __shared__ unsigned rk[256];
    __shared__ int ri[256];

    int bh = blockIdx.x;
    int t = threadIdx.x;
    const float* m = g_M + bh * L_;
    for (int i = t; i < L_; i += 256) skeys[i] = f2key(m[i]);
    hist[t] = 0;
    __syncthreads();

    // level 1: bits 31..24
    for (int i = t; i < L_; i += 256) atomicAdd(&hist[skeys[i] >> 24], 1);
    __syncthreads();
    if (t == 0) {
        int acc = 0;
        for (int bin = 255; bin >= 0; bin--) {
            if (acc + hist[bin] >= U_) { sT1 = bin; sN1 = acc; break; }
            acc += hist[bin];
        }
    }
    __syncthreads();
    int T1 = sT1, n1 = sN1;
    hist[t] = 0;
    __syncthreads();

    // level 2: bits 23..16 within bin T1
    for (int i = t; i < L_; i += 256)
        if ((int)(skeys[i] >> 24) == T1) atomicAdd(&hist[(skeys[i] >> 16) & 255], 1);
    __syncthreads();
    if (t == 0) {
        int acc = n1;
        for (int bin = 255; bin >= 0; bin--) {
            if (acc + hist[bin] >= U_) { sT2 = bin; break; }
            acc += hist[bin];
        }
        cSel = 0; cCand = 0;
    }
    __syncthreads();
    unsigned TH16 = ((unsigned)T1 << 8) | (unsigned)sT2;

    // pass C: definite selects (key16 > TH16) + candidates (key16 == TH16)
    for (int i = t; i < L_; i += 256) {
        unsigned k16 = skeys[i] >> 16;
        if (k16 > TH16) {
            int pos = atomicAdd(&cSel, 1);
            g_Mtop[bh * U_ + pos] = i;
        } else if (k16 == TH16) {
            int pos = atomicAdd(&cCand, 1);
            if (pos < 1024) { candKey[pos] = skeys[i]; candIdx[pos] = i; }
        }
    }
    __syncthreads();
    int ndef = cSel;
    int need = U_ - ndef;
    int nc = (cCand < 1024) ? cCand : 1024;

    // iterative argmax for the remaining `need` picks
    for (int it = 0; it < need; it++) {
        unsigned best = 0; int bi = -1;
        for (int jj = t; jj < nc; jj += 256) {
            unsigned v = candKey[jj];
            if (v > best) { best = v; bi = jj; }
        }
        rk[t] = best; ri[t] = bi;
        __syncthreads();
        for (int s = 128; s; s >>= 1) {
            if (t < s && rk[t + s] > rk[t]) { rk[t] = rk[t + s]; ri[t] = ri[t + s]; }
            __syncthreads();
        }
        if (t == 0) {
            g_Mtop[bh * U_ + ndef + it] = candIdx[ri[0]];
            candKey[ri[0]] = 0;
        }
        __syncthreads();
    }
}

// ---------------------------------------------------------------------------
// Kernel 3: V mean (zero + float4 partial sums, 32 segments per (b,h))
// ---------------------------------------------------------------------------
__global__ void kernel_zero_mean() {
    int i = blockIdx.x * blockDim.x + threadIdx.x;
    if (i < B_ * H_ * D_) g_vmean[i] = 0.0f;
}

__global__ void __launch_bounds__(256) kernel_mean_part(const float* __restrict__ V) {
    int blk = blockIdx.x;              // 1024 blocks
    int seg = blk & 31;
    int bh = blk >> 5;
    int h = bh & (H_ - 1);
    int b = bh >> 3;
    int t = threadIdx.x;
    int d4 = t & 15;
    int sub = t >> 4;                  // 0..15
    int l0 = seg * 128;
    const float4* V4 = (const float4*)V;
    float ax = 0.f, ay = 0.f, az = 0.f, aw = 0.f;
#pragma unroll
    for (int i = 0; i < 8; i++) {
        int l = l0 + sub + i * 16;
        float4 v = V4[((size_t)(b * L_ + l) * H_ + h) * 16 + d4];
        ax += v.x; ay += v.y; az += v.z; aw += v.w;
    }
    __shared__ float4 s[16][16];
    s[sub][d4] = make_float4(ax, ay, az, aw);
    __syncthreads();
    if (t < 16) {
        float tx = 0.f, ty = 0.f, tz = 0.f, tw = 0.f;
#pragma unroll
        for (int jj = 0; jj < 16; jj++) {
            float4 v = s[jj][t];
            tx += v.x; ty += v.y; tz += v.z; tw += v.w;
        }
        atomicAdd(&g_vmean[bh * D_ + t * 4 + 0], tx);
        atomicAdd(&g_vmean[bh * D_ + t * 4 + 1], ty);
        atomicAdd(&g_vmean[bh * D_ + t * 4 + 2], tz);
        atomicAdd(&g_vmean[bh * D_ + t * 4 + 3], tw);
    }
}

// ---------------------------------------------------------------------------
// Kernel 4: fill out with V-mean broadcast (float4 stores, coalesced)
// ---------------------------------------------------------------------------
__global__ void kernel_fill(float* __restrict__ out) {
    unsigned i = blockIdx.x * blockDim.x + threadIdx.x;  // float4 index, < 2^21
    int d4 = i & 15;
    int h = (i >> 4) & 7;
    int b = i >> 19;                   // / (L*H*16)
    const float4* vm4 = (const float4*)g_vmean;
    float4 v = vm4[(b * H_ + h) * 16 + d4];
    const float inv = 1.0f / (float)L_;
    ((float4*)out)[i] = make_float4(v.x * inv, v.y * inv, v.z * inv, v.w * inv);
}

// ---------------------------------------------------------------------------
// Kernel 5: split-KV flash attention over the 45 selected queries per (b,h).
// grid = 32 (bh) x 64 (splits), 256 threads. Partial (m, s, acc) per split.
// ---------------------------------------------------------------------------
__global__ void __launch_bounds__(256) kernel_attn_part(
        const float* __restrict__ Q,
        const float* __restrict__ K,
        const float* __restrict__ V) {
    __shared__ float sQ[UPAD][D_];     // 12 KB (rows >= U_ zeroed)
    __shared__ float sKV[D_][68];      // 17 KB: K as [k][d-padded], then V^T as [d][k]
    __shared__ float sSC[UPAD][68];    // 13 KB scores -> exp weights
    __shared__ int sMtop[U_];

    int bh = blockIdx.x >> 6;
    int sp = blockIdx.x & 63;
    int h = bh & 7, b = bh >> 3;
    int k0 = sp * KC;
    int t = threadIdx.x;

    if (t < U_) sMtop[t] = g_Mtop[bh * U_ + t];
    __syncthreads();

    // Load selected Q rows (zero-pad to 48)
    for (int i = t; i < UPAD * D_; i += 256) {
        int u = i >> 6, d = i & 63;
        sQ[u][d] = (u < U_) ? Q[((b * L_ + sMtop[u]) * H_ + h) * D_ + d] : 0.0f;
    }
    // Load K chunk [KC][D_]
    for (int i = t; i < KC * D_; i += 256) {
        int k = i >> 6, d = i & 63;
        sKV[k][d] = K[((b * L_ + k0 + k) * H_ + h) * D_ + d];
    }
    __syncthreads();

    // Phase 1: scores.  thread = (k = t&63, u-tile of 12)
    {
        int k = t & 63, uq = t >> 6, u0 = uq * 12;
        float acc[12];
#pragma unroll
        for (int jj = 0; jj < 12; jj++) acc[jj] = 0.0f;
#pragma unroll
        for (int d4 = 0; d4 < 16; d4++) {
            float4 kv = *(const float4*)&sKV[k][d4 * 4];
#pragma unroll
            for (int jj = 0; jj < 12; jj++) {
                float4 qv = *(const float4*)&sQ[u0 + jj][d4 * 4];
                acc[jj] += qv.x * kv.x + qv.y * kv.y + qv.z * kv.z + qv.w * kv.w;
            }
        }
#pragma unroll
        for (int jj = 0; jj < 12; jj++) sSC[u0 + jj][k] = acc[jj] * 0.125f;
    }
    __syncthreads();

    // Load V chunk TRANSPOSED into sKV[d][k] (phase-1 K no longer needed)
    for (int i = t; i < KC * D_; i += 256) {
        int k = i >> 6, d = i & 63;
        sKV[d][k] = V[((b * L_ + k0 + k) * H_ + h) * D_ + d];
    }

    // Phase 2: per-u local max/expsum over the 64 keys; exp in place
    {
        int wp = t >> 5, lane = t & 31;
        for (int i = 0; i < 6; i++) {
            int u = wp + i * 8;
            if (u < U_) {
                float v0 = sSC[u][lane], v1 = sSC[u][lane + 32];
                float mm = fmaxf(v0, v1);
                for (int o = 16; o; o >>= 1) mm = fmaxf(mm, __shfl_xor_sync(0xffffffffu, mm, o));
                float e0 = __expf(v0 - mm), e1 = __expf(v1 - mm);
                float ss = e0 + e1;
                for (int o = 16; o; o >>= 1) ss += __shfl_xor_sync(0xffffffffu, ss, o);
                sSC[u][lane] = e0;
                sSC[u][lane + 32] = e1;
                if (lane == 0) {
                    g_pm[(bh * NSPLIT + sp) * U_ + u] = mm;
                    g_ps[(bh * NSPLIT + sp) * U_ + u] = ss;
                }
            }
        }
    }
    __syncthreads();

    // Phase 3: partial AV.  thread = (d = t&63, u-tile of 12)
    {
        int d = t & 63, uq = t >> 6, u0 = uq * 12;
        int nu = (uq == 3) ? 9 : 12;
        float acc[12];
#pragma unroll
        for (int jj = 0; jj < 12; jj++) acc[jj] = 0.0f;
#pragma unroll
        for (int k4 = 0; k4 < 16; k4++) {
            float4 v4 = *(const float4*)&sKV[d][k4 * 4];
            for (int jj = 0; jj < nu; jj++) {
                float4 e4 = *(const float4*)&sSC[u0 + jj][k4 * 4];
                acc[jj] += e4.x * v4.x + e4.y * v4.y + e4.z * v4.z + e4.w * v4.w;
            }
        }
        float* pa = g_pacc + (size_t)(bh * NSPLIT + sp) * U_ * D_;
        for (int jj = 0; jj < nu; jj++) pa[(u0 + jj) * D_ + d] = acc[jj];
    }
}

// ---------------------------------------------------------------------------
// Kernel 6: combine split partials + scatter into output. grid = 32 (bh).
// ---------------------------------------------------------------------------
__global__ void __launch_bounds__(256) kernel_combine(float* __restrict__ out) {
    __shared__ float sf[U_][NSPLIT];   // 11.5 KB per-split weights
    __shared__ int sMtop[U_];
    int bh = blockIdx.x;
    int h = bh & 7, b = bh >> 3;
    int t = threadIdx.x;
    if (t < U_) sMtop[t] = g_Mtop[bh * U_ + t];
    {
        int wp = t >> 5, lane = t & 31;
        for (int i = 0; i < 6; i++) {
            int u = wp + i * 8;
            if (u < U_) {
                float m0 = g_pm[(bh * NSPLIT + lane) * U_ + u];
                float m1 = g_pm[(bh * NSPLIT + lane + 32) * U_ + u];
                float mm = fmaxf(m0, m1);
                for (int o = 16; o; o >>= 1) mm = fmaxf(mm, __shfl_xor_sync(0xffffffffu, mm, o));
                float e0 = __expf(m0 - mm), e1 = __expf(m1 - mm);
                float ss = e0 * g_ps[(bh * NSPLIT + lane) * U_ + u]
                         + e1 * g_ps[(bh * NSPLIT + lane + 32) * U_ + u];
                for (int o = 16; o; o >>= 1) ss += __shfl_xor_sync(0xffffffffu, ss, o);
                float inv = 1.0f / ss;
                sf[u][lane] = e0 * inv;
                sf[u][lane + 32] = e1 * inv;
            }
        }
    }
    __syncthreads();
    int d = t & 63, ug = t >> 6;
    for (int u = ug; u < U_; u += 4) {
        float acc = 0.0f;
        const float* pa = g_pacc + (size_t)bh * NSPLIT * U_ * D_ + u * D_ + d;
#pragma unroll 8
        for (int sp = 0; sp < NSPLIT; sp++)
            acc += pa[(size_t)sp * U_ * D_] * sf[u][sp];
        out[((b * L_ + sMtop[u]) * H_ + h) * D_ + d] = acc;
    }
}

// ---------------------------------------------------------------------------
extern "C" void kernel_launch(void* const* d_in, const int* in_sizes, int n_in,
                              void* d_out, int out_size) {
    const float* Q = (const float*)d_in[0];
    const float* K = (const float*)d_in[1];
    const float* V = (const float*)d_in[2];
    const int* idx = (const int*)d_in[3];   // int32 (JAX x64 disabled)
    float* out = (float*)d_out;

    // Max-L1 carveout for the gather kernel (no smem use there)
    cudaFuncSetAttribute((const void*)kernel_M,
                         cudaFuncAttributePreferredSharedMemoryCarveout, 0);

    // Order chosen so the ncu capture slot (4th launch) lands on kernel_M.
    kernel_zero_mean<<<(B_ * H_ * D_ + 255) / 256, 256>>>();
    kernel_mean_part<<<B_ * H_ * 32, 256>>>(V);
    kernel_fill<<<(B_ * L_ * H_ * D_ / 4 + 255) / 256, 256>>>(out);
    kernel_M<<<(B_ * H_ * L_) / 8, 256>>>(Q, K, idx);
    kernel_topk<<<B_ * H_, 256>>>();
    kernel_attn_part<<<B_ * H_ * NSPLIT, 256>>>(Q, K, V);
    kernel_combine<<<B_ * H_, 256>>>(out);
}

// round 5
// speedup vs baseline: 2.7452x; 1.3202x over previous
#include <cuda_runtime.h>
#include <math_constants.h>

// ProbAttention: B=4, L=4096, H=8, D=64, FACTOR=5
#define B_ 4
#define L_ 4096
#define H_ 8
#define D_ 64
#define SK_ 45
#define U_  45
#define NSPLIT 64
#define KC 64          // keys per split = L_/NSPLIT
#define PADK 68

// Scratch (device globals; no allocation allowed)
__device__ float g_M[B_ * H_ * L_];
__device__ int   g_Mtop[B_ * H_ * U_];
__device__ float g_vmean[B_ * H_ * D_];
__device__ float g_pm[B_ * H_ * NSPLIT * U_];
__device__ float g_ps[B_ * H_ * NSPLIT * U_];
__device__ float g_pacc[B_ * H_ * NSPLIT * U_ * D_];   // 23.6 MB

typedef unsigned long long ull;
__device__ __forceinline__ ull dup2(float x) {
    unsigned u = __float_as_uint(x);
    return ((ull)u << 32) | (ull)u;
}
__device__ __forceinline__ float lo2(ull v) { return __uint_as_float((unsigned)v); }
__device__ __forceinline__ float hi2(ull v) { return __uint_as_float((unsigned)(v >> 32)); }
#define FMA2(acc, a, b) asm("fma.rn.f32x2 %0, %1, %2, %0;" : "+l"(acc) : "l"(a), "l"(b))

// ---------------------------------------------------------------------------
// Kernel 1: M[b,h,l] = max_s(Q·K_s) - (1/L)*sum_s(Q·K_s)
// One warp per (b,h,l); 4 samples in flight (8 lanes per 256B K row).
// ---------------------------------------------------------------------------
__global__ void __launch_bounds__(256) kernel_M(const float* __restrict__ Q,
                                                const float* __restrict__ K,
                                                const int* __restrict__ idx) {
    int j = (blockIdx.x * 111) & 16383;      // bijective remap (gcd(111,16384)=1)
    int w = j * 8 + (threadIdx.x >> 5);      // [0, B*H*L)
    int lane = threadIdx.x & 31;
    int li = lane & 7;
    int g  = lane >> 3;
    int l = w & (L_ - 1);
    int h = (w >> 12) & (H_ - 1);
    int b = w >> 15;

    const float4* q4 = (const float4*)(Q + ((b * L_ + l) * H_ + h) * D_);
    float4 qa = q4[li * 2];
    float4 qb = q4[li * 2 + 1];

    const int* ip = idx + l * SK_;
    float mx = -CUDART_INF_F;
    float sm = 0.0f;
#pragma unroll
    for (int sg = 0; sg < 12; sg++) {
        int s = sg * 4 + g;
        bool valid = (s < SK_);
        int kr = ip[valid ? s : 0];
        const float4* k4 = (const float4*)(K + ((b * L_ + kr) * H_ + h) * D_);
        float4 ka = k4[li * 2];
        float4 kb = k4[li * 2 + 1];
        float d = qa.x * ka.x + qa.y * ka.y + qa.z * ka.z + qa.w * ka.w
                + qb.x * kb.x + qb.y * kb.y + qb.z * kb.z + qb.w * kb.w;
        d += __shfl_xor_sync(0xffffffffu, d, 4);
        d += __shfl_xor_sync(0xffffffffu, d, 2);
        d += __shfl_xor_sync(0xffffffffu, d, 1);
        if (valid) { mx = fmaxf(mx, d); sm += d; }
    }
    mx = fmaxf(mx, __shfl_xor_sync(0xffffffffu, mx, 8));
    mx = fmaxf(mx, __shfl_xor_sync(0xffffffffu, mx, 16));
    sm += __shfl_xor_sync(0xffffffffu, sm, 8);
    sm += __shfl_xor_sync(0xffffffffu, sm, 16);
    if (lane == 0) g_M[w] = mx - sm * (1.0f / (float)L_);
}

// ---------------------------------------------------------------------------
// Kernel 2: top-U per (b,h): two-level radix histogram + exact tail select.
// ---------------------------------------------------------------------------
__device__ __forceinline__ unsigned f2key(float f) {
    unsigned u = __float_as_uint(f);
    return (u & 0x80000000u) ? ~u : (u | 0x80000000u);
}

__global__ void __launch_bounds__(256) kernel_topk() {
    __shared__ unsigned skeys[L_];
    __shared__ int hist[256];
    __shared__ unsigned candKey[1024];
    __shared__ int candIdx[1024];
    __shared__ int sT1, sN1, sT2;
    __shared__ int cSel, cCand;
    __shared__ unsigned rk[256];
    __shared__ int ri[256];

    int bh = blockIdx.x;
    int t = threadIdx.x;
    const float* m = g_M + bh * L_;
    for (int i = t; i < L_; i += 256) skeys[i] = f2key(m[i]);
    hist[t] = 0;
    __syncthreads();

    for (int i = t; i < L_; i += 256) atomicAdd(&hist[skeys[i] >> 24], 1);
    __syncthreads();
    if (t == 0) {
        int acc = 0;
        for (int bin = 255; bin >= 0; bin--) {
            if (acc + hist[bin] >= U_) { sT1 = bin; sN1 = acc; break; }
            acc += hist[bin];
        }
    }
    __syncthreads();
    int T1 = sT1, n1 = sN1;
    hist[t] = 0;
    __syncthreads();

    for (int i = t; i < L_; i += 256)
        if ((int)(skeys[i] >> 24) == T1) atomicAdd(&hist[(skeys[i] >> 16) & 255], 1);
    __syncthreads();
    if (t == 0) {
        int acc = n1;
        for (int bin = 255; bin >= 0; bin--) {
            if (acc + hist[bin] >= U_) { sT2 = bin; break; }
            acc += hist[bin];
        }
        cSel = 0; cCand = 0;
    }
    __syncthreads();
    unsigned TH16 = ((unsigned)T1 << 8) | (unsigned)sT2;

    for (int i = t; i < L_; i += 256) {
        unsigned k16 = skeys[i] >> 16;
        if (k16 > TH16) {
            int pos = atomicAdd(&cSel, 1);
            g_Mtop[bh * U_ + pos] = i;
        } else if (k16 == TH16) {
            int pos = atomicAdd(&cCand, 1);
            if (pos < 1024) { candKey[pos] = skeys[i]; candIdx[pos] = i; }
        }
    }
    __syncthreads();
    int ndef = cSel;
    int need = U_ - ndef;
    int nc = (cCand < 1024) ? cCand : 1024;

    for (int it = 0; it < need; it++) {
        unsigned best = 0; int bi = -1;
        for (int jj = t; jj < nc; jj += 256) {
            unsigned v = candKey[jj];
            if (v > best) { best = v; bi = jj; }
        }
        rk[t] = best; ri[t] = bi;
        __syncthreads();
        for (int s = 128; s; s >>= 1) {
            if (t < s && rk[t + s] > rk[t]) { rk[t] = rk[t + s]; ri[t] = ri[t + s]; }
            __syncthreads();
        }
        if (t == 0) {
            g_Mtop[bh * U_ + ndef + it] = candIdx[ri[0]];
            candKey[ri[0]] = 0;
        }
        __syncthreads();
    }
}

// ---------------------------------------------------------------------------
// Kernel 3: V mean (zero + float4 partial sums)
// ---------------------------------------------------------------------------
__global__ void kernel_zero_mean() {
    int i = blockIdx.x * blockDim.x + threadIdx.x;
    if (i < B_ * H_ * D_) g_vmean[i] = 0.0f;
}

__global__ void __launch_bounds__(256) kernel_mean_part(const float* __restrict__ V) {
    int blk = blockIdx.x;              // 1024 blocks
    int seg = blk & 31;
    int bh = blk >> 5;
    int h = bh & (H_ - 1);
    int b = bh >> 3;
    int t = threadIdx.x;
    int d4 = t & 15;
    int sub = t >> 4;
    int l0 = seg * 128;
    const float4* V4 = (const float4*)V;
    float ax = 0.f, ay = 0.f, az = 0.f, aw = 0.f;
#pragma unroll
    for (int i = 0; i < 8; i++) {
        int l = l0 + sub + i * 16;
        float4 v = V4[((size_t)(b * L_ + l) * H_ + h) * 16 + d4];
        ax += v.x; ay += v.y; az += v.z; aw += v.w;
    }
    __shared__ float4 s[16][16];
    s[sub][d4] = make_float4(ax, ay, az, aw);
    __syncthreads();
    if (t < 16) {
        float tx = 0.f, ty = 0.f, tz = 0.f, tw = 0.f;
#pragma unroll
        for (int jj = 0; jj < 16; jj++) {
            float4 v = s[jj][t];
            tx += v.x; ty += v.y; tz += v.z; tw += v.w;
        }
        atomicAdd(&g_vmean[bh * D_ + t * 4 + 0], tx);
        atomicAdd(&g_vmean[bh * D_ + t * 4 + 1], ty);
        atomicAdd(&g_vmean[bh * D_ + t * 4 + 2], tz);
        atomicAdd(&g_vmean[bh * D_ + t * 4 + 3], tw);
    }
}

// ---------------------------------------------------------------------------
// Kernel 4: fill out with V-mean broadcast (float4 stores)
// ---------------------------------------------------------------------------
__global__ void kernel_fill(float* __restrict__ out) {
    unsigned i = blockIdx.x * blockDim.x + threadIdx.x;  // float4 index
    int d4 = i & 15;
    int h = (i >> 4) & 7;
    int b = i >> 19;
    const float4* vm4 = (const float4*)g_vmean;
    float4 v = vm4[(b * H_ + h) * 16 + d4];
    const float inv = 1.0f / (float)L_;
    ((float4*)out)[i] = make_float4(v.x * inv, v.y * inv, v.z * inv, v.w * inv);
}

// ---------------------------------------------------------------------------
// Kernel 5: split-KV attention, register-tiled, f32x2-packed FMA.
// grid = 32 (bh) x 64 (splits), 256 threads.
// Dynamic smem layout:
//   sKT  [64][PADK] floats : K transposed [d][k], later V natural [k][d]
//   sSC  [48][PADK] floats : scores -> (phase2 reads)
//   sQE  [48][64]  ull     : Q duplicated pairs, later E duplicated pairs
//   sMt  [64] int
// ---------------------------------------------------------------------------
#define OFF_SC  (64 * PADK)               // floats
#define OFF_QE  (OFF_SC + 48 * PADK)      // floats (8-aligned: 17408+13056 B)
#define SMEM_BYTES (OFF_QE * 4 + 48 * 64 * 8 + 256)

__global__ void __launch_bounds__(256) kernel_attn_part(
        const float* __restrict__ Q,
        const float* __restrict__ K,
        const float* __restrict__ V) {
    extern __shared__ float smem[];
    float* sKT = smem;                          // [64][PADK]
    float* sSC = smem + OFF_SC;                 // [48][PADK]
    ull*   sQE = (ull*)(smem + OFF_QE);         // [48][64]
    int*   sMt = (int*)(sQE + 48 * 64);

    int bh = blockIdx.x >> 6;
    int sp = blockIdx.x & 63;
    int h = bh & 7, b = bh >> 3;
    int k0 = sp * KC;
    int t = threadIdx.x;

    if (t < U_) sMt[t] = g_Mtop[bh * U_ + t];
    __syncthreads();

    // Fill Q duplicated (rows >= U_ zero)
    for (int i = t; i < 48 * 64; i += 256) {
        int u = i >> 6, d = i & 63;
        float q = (u < U_) ? Q[((b * L_ + sMt[u]) * H_ + h) * D_ + d] : 0.0f;
        sQE[i] = dup2(q);
    }
    // Fill K transposed
    for (int i = t; i < KC * D_; i += 256) {
        int k = i >> 6, d = i & 63;
        sKT[d * PADK + k] = K[((b * L_ + k0 + k) * H_ + h) * D_ + d];
    }
    __syncthreads();

    int kt = t & 15, ut = t >> 4;
    int kk = kt * 4, u0 = ut * 3;

    // Phase 1: scores S[u][k] = sum_d q[u][d]*k[d][k], f32x2 over k-pairs
    {
        ull a00 = 0, a01 = 0, a10 = 0, a11 = 0, a20 = 0, a21 = 0;
        const ull* q0p = &sQE[(u0 + 0) * 64];
        const ull* q1p = &sQE[(u0 + 1) * 64];
        const ull* q2p = &sQE[(u0 + 2) * 64];
#pragma unroll 8
        for (int d = 0; d < 64; d++) {
            ulonglong2 kv = *(const ulonglong2*)&sKT[d * PADK + kk];
            ull q0 = q0p[d], q1 = q1p[d], q2 = q2p[d];
            FMA2(a00, q0, kv.x); FMA2(a01, q0, kv.y);
            FMA2(a10, q1, kv.x); FMA2(a11, q1, kv.y);
            FMA2(a20, q2, kv.x); FMA2(a21, q2, kv.y);
        }
        const float sc = 0.125f;
        *(float4*)&sSC[(u0 + 0) * PADK + kk] =
            make_float4(lo2(a00) * sc, hi2(a00) * sc, lo2(a01) * sc, hi2(a01) * sc);
        *(float4*)&sSC[(u0 + 1) * PADK + kk] =
            make_float4(lo2(a10) * sc, hi2(a10) * sc, lo2(a11) * sc, hi2(a11) * sc);
        *(float4*)&sSC[(u0 + 2) * PADK + kk] =
            make_float4(lo2(a20) * sc, hi2(a20) * sc, lo2(a21) * sc, hi2(a21) * sc);
    }
    __syncthreads();

    // Fill V natural [k][d] into sKT region (K dead)
    for (int i = t; i < KC * D_; i += 256) {
        int k = i >> 6, d = i & 63;
        sKT[k * PADK + d] = V[((b * L_ + k0 + k) * H_ + h) * D_ + d];
    }

    // Phase 2: per-u softmax partials over 64 keys; write duplicated E
    {
        int wp = t >> 5, lane = t & 31;
        for (int i = 0; i < 6; i++) {
            int u = wp + i * 8;
            if (u < U_) {
                float v0 = sSC[u * PADK + lane], v1 = sSC[u * PADK + lane + 32];
                float mm = fmaxf(v0, v1);
                for (int o = 16; o; o >>= 1) mm = fmaxf(mm, __shfl_xor_sync(0xffffffffu, mm, o));
                float e0 = __expf(v0 - mm), e1 = __expf(v1 - mm);
                float ss = e0 + e1;
                for (int o = 16; o; o >>= 1) ss += __shfl_xor_sync(0xffffffffu, ss, o);
                sQE[u * 64 + lane] = dup2(e0);
                sQE[u * 64 + lane + 32] = dup2(e1);
                if (lane == 0) {
                    g_pm[(bh * NSPLIT + sp) * U_ + u] = mm;
                    g_ps[(bh * NSPLIT + sp) * U_ + u] = ss;
                }
            }
        }
    }
    __syncthreads();

    // Phase 3: partial AV[u][d] = sum_k E[u][k]*V[k][d], f32x2 over d-pairs
    {
        int dt = t & 15, ut2 = t >> 4;
        int dd = dt * 4, uu0 = ut2 * 3;
        ull a00 = 0, a01 = 0, a10 = 0, a11 = 0, a20 = 0, a21 = 0;
        const ull* e0p = &sQE[(uu0 + 0) * 64];
        const ull* e1p = &sQE[(uu0 + 1) * 64];
        const ull* e2p = &sQE[(uu0 + 2) * 64];
#pragma unroll 8
        for (int k = 0; k < 64; k++) {
            ulonglong2 vv = *(const ulonglong2*)&sKT[k * PADK + dd];
            ull e0 = e0p[k], e1 = e1p[k], e2 = e2p[k];
            FMA2(a00, e0, vv.x); FMA2(a01, e0, vv.y);
            FMA2(a10, e1, vv.x); FMA2(a11, e1, vv.y);
            FMA2(a20, e2, vv.x); FMA2(a21, e2, vv.y);
        }
        float* pa = g_pacc + (size_t)(bh * NSPLIT + sp) * U_ * D_;
        if (uu0 + 0 < U_)
            *(float4*)&pa[(uu0 + 0) * D_ + dd] =
                make_float4(lo2(a00), hi2(a00), lo2(a01), hi2(a01));
        if (uu0 + 1 < U_)
            *(float4*)&pa[(uu0 + 1) * D_ + dd] =
                make_float4(lo2(a10), hi2(a10), lo2(a11), hi2(a11));
        if (uu0 + 2 < U_)
            *(float4*)&pa[(uu0 + 2) * D_ + dd] =
                make_float4(lo2(a20), hi2(a20), lo2(a21), hi2(a21));
    }
}

// ---------------------------------------------------------------------------
// Kernel 6: combine partials. grid = (U_, B*H), 64 threads (sp then d role).
// ---------------------------------------------------------------------------
__global__ void __launch_bounds__(64) kernel_combine(float* __restrict__ out) {
    __shared__ float sw[NSPLIT];
    __shared__ float red[64];
    int u = blockIdx.x;
    int bh = blockIdx.y;
    int h = bh & 7, b = bh >> 3;
    int t = threadIdx.x;

    float m = g_pm[(bh * NSPLIT + t) * U_ + u];
    float s = g_ps[(bh * NSPLIT + t) * U_ + u];
    red[t] = m;
    __syncthreads();
    for (int st = 32; st; st >>= 1) {
        if (t < st) red[t] = fmaxf(red[t], red[t + st]);
        __syncthreads();
    }
    float M = red[0];
    __syncthreads();
    float e = __expf(m - M);
    red[t] = e * s;
    __syncthreads();
    for (int st = 32; st; st >>= 1) {
        if (t < st) red[t] += red[t + st];
        __syncthreads();
    }
    float inv = 1.0f / red[0];
    sw[t] = e * inv;
    __syncthreads();

    float acc = 0.0f;
    const float* pa = g_pacc + (size_t)bh * NSPLIT * U_ * D_ + u * D_ + t;
#pragma unroll 8
    for (int sp = 0; sp < NSPLIT; sp++)
        acc += pa[(size_t)sp * U_ * D_] * sw[sp];
    int lsel = g_Mtop[bh * U_ + u];
    out[((b * L_ + lsel) * H_ + h) * D_ + t] = acc;
}

// ---------------------------------------------------------------------------
extern "C" void kernel_launch(void* const* d_in, const int* in_sizes, int n_in,
                              void* d_out, int out_size) {
    const float* Q = (const float*)d_in[0];
    const float* K = (const float*)d_in[1];
    const float* V = (const float*)d_in[2];
    const int* idx = (const int*)d_in[3];   // int32 (JAX x64 disabled)
    float* out = (float*)d_out;

    cudaFuncSetAttribute((const void*)kernel_M,
                         cudaFuncAttributePreferredSharedMemoryCarveout, 0);
    cudaFuncSetAttribute((const void*)kernel_attn_part,
                         cudaFuncAttributeMaxDynamicSharedMemorySize, SMEM_BYTES);

    // Order: ncu capture slot (4th launch) lands on kernel_attn_part.
    kernel_M<<<(B_ * H_ * L_) / 8, 256>>>(Q, K, idx);
    kernel_topk<<<B_ * H_, 256>>>();
    kernel_zero_mean<<<(B_ * H_ * D_ + 255) / 256, 256>>>();
    kernel_attn_part<<<B_ * H_ * NSPLIT, 256, SMEM_BYTES>>>(Q, K, V);
    kernel_mean_part<<<B_ * H_ * 32, 256>>>(V);
    kernel_fill<<<(B_ * L_ * H_ * D_ / 4 + 255) / 256, 256>>>(out);
    kernel_combine<<<dim3(U_, B_ * H_), 64>>>(out);
}

// round 6
// speedup vs baseline: 3.3045x; 1.2038x over previous
#include <cuda_runtime.h>
#include <math_constants.h>

// ProbAttention: B=4, L=4096, H=8, D=64, FACTOR=5
#define B_ 4
#define L_ 4096
#define H_ 8
#define D_ 64
#define SK_ 45
#define U_  45
#define NSPLIT 64
#define KC 64          // keys per split = L_/NSPLIT
#define PADK 68

// Scratch (device globals; no allocation allowed)
__device__ float g_M[B_ * H_ * L_];
__device__ int   g_Mtop[B_ * H_ * U_];
__device__ float g_vmean[B_ * H_ * D_];
__device__ float g_pm[B_ * H_ * NSPLIT * U_];
__device__ float g_ps[B_ * H_ * NSPLIT * U_];
__device__ float g_pacc[B_ * H_ * NSPLIT * U_ * D_];   // 23.6 MB

typedef unsigned long long ull;
__device__ __forceinline__ float lo2(ull v) { return __uint_as_float((unsigned)v); }
__device__ __forceinline__ float hi2(ull v) { return __uint_as_float((unsigned)(v >> 32)); }
#define FMA2(acc, a, b) asm("fma.rn.f32x2 %0, %1, %2, %0;" : "+l"(acc) : "l"(a), "l"(b))
#define DUP2(out, x) asm("mov.b64 %0, {%1, %1};" : "=l"(out) : "r"(__float_as_uint(x)))

__device__ __forceinline__ unsigned smem_u32(const void* p) {
    return (unsigned)__cvta_generic_to_shared(p);
}

// ---------------------------------------------------------------------------
// Kernel 1: M[b,h,l] = max_s(Q·K_s) - (1/L)*sum_s(Q·K_s)
// At the L2 roofline (1.51 GB gather @ ~12 TB/s). Unchanged.
// ---------------------------------------------------------------------------
__global__ void __launch_bounds__(256) kernel_M(const float* __restrict__ Q,
                                                const float* __restrict__ K,
                                                const int* __restrict__ idx) {
    int j = (blockIdx.x * 111) & 16383;      // bijective remap
    int w = j * 8 + (threadIdx.x >> 5);
    int lane = threadIdx.x & 31;
    int li = lane & 7;
    int g  = lane >> 3;
    int l = w & (L_ - 1);
    int h = (w >> 12) & (H_ - 1);
    int b = w >> 15;

    const float4* q4 = (const float4*)(Q + ((b * L_ + l) * H_ + h) * D_);
    float4 qa = q4[li * 2];
    float4 qb = q4[li * 2 + 1];

    const int* ip = idx + l * SK_;
    float mx = -CUDART_INF_F;
    float sm = 0.0f;
#pragma unroll
    for (int sg = 0; sg < 12; sg++) {
        int s = sg * 4 + g;
        bool valid = (s < SK_);
        int kr = ip[valid ? s : 0];
        const float4* k4 = (const float4*)(K + ((b * L_ + kr) * H_ + h) * D_);
        float4 ka = k4[li * 2];
        float4 kb = k4[li * 2 + 1];
        float d = qa.x * ka.x + qa.y * ka.y + qa.z * ka.z + qa.w * ka.w
                + qb.x * kb.x + qb.y * kb.y + qb.z * kb.z + qb.w * kb.w;
        d += __shfl_xor_sync(0xffffffffu, d, 4);
        d += __shfl_xor_sync(0xffffffffu, d, 2);
        d += __shfl_xor_sync(0xffffffffu, d, 1);
        if (valid) { mx = fmaxf(mx, d); sm += d; }
    }
    mx = fmaxf(mx, __shfl_xor_sync(0xffffffffu, mx, 8));
    mx = fmaxf(mx, __shfl_xor_sync(0xffffffffu, mx, 16));
    sm += __shfl_xor_sync(0xffffffffu, sm, 8);
    sm += __shfl_xor_sync(0xffffffffu, sm, 16);
    if (lane == 0) g_M[w] = mx - sm * (1.0f / (float)L_);
}

// ---------------------------------------------------------------------------
// Kernel 2: top-U per (b,h): two-level radix histogram + exact tail select.
// ---------------------------------------------------------------------------
__device__ __forceinline__ unsigned f2key(float f) {
    unsigned u = __float_as_uint(f);
    return (u & 0x80000000u) ? ~u : (u | 0x80000000u);
}

__global__ void __launch_bounds__(256) kernel_topk() {
    __shared__ unsigned skeys[L_];
    __shared__ int hist[256];
    __shared__ unsigned candKey[1024];
    __shared__ int candIdx[1024];
    __shared__ int sT1, sN1, sT2;
    __shared__ int cSel, cCand;
    __shared__ unsigned rk[256];
    __shared__ int ri[256];

    int bh = blockIdx.x;
    int t = threadIdx.x;
    const float* m = g_M + bh * L_;
    for (int i = t; i < L_; i += 256) skeys[i] = f2key(m[i]);
    hist[t] = 0;
    __syncthreads();

    for (int i = t; i < L_; i += 256) atomicAdd(&hist[skeys[i] >> 24], 1);
    __syncthreads();
    if (t == 0) {
        int acc = 0;
        for (int bin = 255; bin >= 0; bin--) {
            if (acc + hist[bin] >= U_) { sT1 = bin; sN1 = acc; break; }
            acc += hist[bin];
        }
    }
    __syncthreads();
    int T1 = sT1, n1 = sN1;
    hist[t] = 0;
    __syncthreads();

    for (int i = t; i < L_; i += 256)
        if ((int)(skeys[i] >> 24) == T1) atomicAdd(&hist[(skeys[i] >> 16) & 255], 1);
    __syncthreads();
    if (t == 0) {
        int acc = n1;
        for (int bin = 255; bin >= 0; bin--) {
            if (acc + hist[bin] >= U_) { sT2 = bin; break; }
            acc += hist[bin];
        }
        cSel = 0; cCand = 0;
    }
    __syncthreads();
    unsigned TH16 = ((unsigned)T1 << 8) | (unsigned)sT2;

    for (int i = t; i < L_; i += 256) {
        unsigned k16 = skeys[i] >> 16;
        if (k16 > TH16) {
            int pos = atomicAdd(&cSel, 1);
            g_Mtop[bh * U_ + pos] = i;
        } else if (k16 == TH16) {
            int pos = atomicAdd(&cCand, 1);
            if (pos < 1024) { candKey[pos] = skeys[i]; candIdx[pos] = i; }
        }
    }
    __syncthreads();
    int ndef = cSel;
    int need = U_ - ndef;
    int nc = (cCand < 1024) ? cCand : 1024;

    for (int it = 0; it < need; it++) {
        unsigned best = 0; int bi = -1;
        for (int jj = t; jj < nc; jj += 256) {
            unsigned v = candKey[jj];
            if (v > best) { best = v; bi = jj; }
        }
        rk[t] = best; ri[t] = bi;
        __syncthreads();
        for (int s = 128; s; s >>= 1) {
            if (t < s && rk[t + s] > rk[t]) { rk[t] = rk[t + s]; ri[t] = ri[t + s]; }
            __syncthreads();
        }
        if (t == 0) {
            g_Mtop[bh * U_ + ndef + it] = candIdx[ri[0]];
            candKey[ri[0]] = 0;
        }
        __syncthreads();
    }
}

// ---------------------------------------------------------------------------
// Kernel 3: V mean (zero + float4 partial sums)
// ---------------------------------------------------------------------------
__global__ void kernel_zero_mean() {
    int i = blockIdx.x * blockDim.x + threadIdx.x;
    if (i < B_ * H_ * D_) g_vmean[i] = 0.0f;
}

__global__ void __launch_bounds__(256) kernel_mean_part(const float* __restrict__ V) {
    int blk = blockIdx.x;              // 1024 blocks
    int seg = blk & 31;
    int bh = blk >> 5;
    int h = bh & (H_ - 1);
    int b = bh >> 3;
    int t = threadIdx.x;
    int d4 = t & 15;
    int sub = t >> 4;
    int l0 = seg * 128;
    const float4* V4 = (const float4*)V;
    float ax = 0.f, ay = 0.f, az = 0.f, aw = 0.f;
#pragma unroll
    for (int i = 0; i < 8; i++) {
        int l = l0 + sub + i * 16;
        float4 v = V4[((size_t)(b * L_ + l) * H_ + h) * 16 + d4];
        ax += v.x; ay += v.y; az += v.z; aw += v.w;
    }
    __shared__ float4 s[16][16];
    s[sub][d4] = make_float4(ax, ay, az, aw);
    __syncthreads();
    if (t < 16) {
        float tx = 0.f, ty = 0.f, tz = 0.f, tw = 0.f;
#pragma unroll
        for (int jj = 0; jj < 16; jj++) {
            float4 v = s[jj][t];
            tx += v.x; ty += v.y; tz += v.z; tw += v.w;
        }
        atomicAdd(&g_vmean[bh * D_ + t * 4 + 0], tx);
        atomicAdd(&g_vmean[bh * D_ + t * 4 + 1], ty);
        atomicAdd(&g_vmean[bh * D_ + t * 4 + 2], tz);
        atomicAdd(&g_vmean[bh * D_ + t * 4 + 3], tw);
    }
}

// ---------------------------------------------------------------------------
// Kernel 4: fill out with V-mean broadcast (float4 stores)
// ---------------------------------------------------------------------------
__global__ void kernel_fill(float* __restrict__ out) {
    unsigned i = blockIdx.x * blockDim.x + threadIdx.x;  // float4 index
    int d4 = i & 15;
    int h = (i >> 4) & 7;
    int b = i >> 19;
    const float4* vm4 = (const float4*)g_vmean;
    float4 v = vm4[(b * H_ + h) * 16 + d4];
    const float inv = 1.0f / (float)L_;
    ((float4*)out)[i] = make_float4(v.x * inv, v.y * inv, v.z * inv, v.w * inv);
}

// ---------------------------------------------------------------------------
// Kernel 5: split-KV attention, de-serialized:
//   - V prefetched via cp.async into its own buffer (overlaps phase 1)
//   - softmax in registers (half-warp butterflies), no smem round trip
// smem: sKT [64][68] | sV [64][68] | sQE [48][64] (Q, then E) | sMt
// ---------------------------------------------------------------------------
#define OFF_V   (64 * PADK)                 // floats
#define OFF_QE  (OFF_V + 64 * PADK)
#define OFF_MT  (OFF_QE + 48 * 64)
#define SMEM_FLOATS (OFF_MT + 64)
#define SMEM_BYTES  (SMEM_FLOATS * 4)

__global__ void __launch_bounds__(256) kernel_attn_part(
        const float* __restrict__ Q,
        const float* __restrict__ K,
        const float* __restrict__ V) {
    extern __shared__ float smem[];
    float* sKT = smem;                  // [64][PADK]  K transposed [d][k]
    float* sV  = smem + OFF_V;          // [64][PADK]  V natural   [k][d]
    float* sQE = smem + OFF_QE;         // [48][64]    Q rows, then E rows
    int*   sMt = (int*)(smem + OFF_MT);

    int bh = blockIdx.x >> 6;
    int sp = blockIdx.x & 63;
    int h = bh & 7, b = bh >> 3;
    int k0 = sp * KC;
    int t = threadIdx.x;

    // Prefetch V (16B cp.async x4 per thread) — consumed only in phase 3.
    {
        const char* vbase = (const char*)(V + ((size_t)(b * L_ + k0) * H_ + h) * D_);
#pragma unroll
        for (int i = 0; i < 4; i++) {
            int e = t + i * 256;              // [0,1024)
            int row = e >> 4, c = e & 15;
            unsigned dst = smem_u32(sV + row * PADK + c * 4);
            const char* src = vbase + (size_t)row * (H_ * D_ * 4) + c * 16;
            asm volatile("cp.async.cg.shared.global [%0], [%1], 16;"
                         :: "r"(dst), "l"(src));
        }
        asm volatile("cp.async.commit_group;");
    }

    if (t < U_) sMt[t] = g_Mtop[bh * U_ + t];
    __syncthreads();

    // Q rows (scattered gather, zero-pad to 48)
#pragma unroll
    for (int i = 0; i < 3; i++) {
        int e = t + i * 256;                  // [0,768)
        int u = e >> 4, c = e & 15;
        float4 q = make_float4(0.f, 0.f, 0.f, 0.f);
        if (u < U_)
            q = *(const float4*)(Q + ((b * L_ + sMt[u]) * H_ + h) * D_ + c * 4);
        *(float4*)(sQE + u * 64 + c * 4) = q;
    }
    // K transposed
#pragma unroll
    for (int i = 0; i < 16; i++) {
        int e = t + i * 256;
        int k = e >> 6, d = e & 63;
        sKT[d * PADK + k] = K[((b * L_ + k0 + k) * H_ + h) * D_ + d];
    }
    __syncthreads();

    int kt = t & 15, ut = t >> 4;
    int kk = kt * 4, u0 = ut * 3;

    // Phase 1: S[u][k] = sum_d q[u][d]*k[d][k]  (3u x 4k per thread)
    ull a00 = 0, a01 = 0, a10 = 0, a11 = 0, a20 = 0, a21 = 0;
    {
        const float* q0p = sQE + (u0 + 0) * 64;
        const float* q1p = sQE + (u0 + 1) * 64;
        const float* q2p = sQE + (u0 + 2) * 64;
#pragma unroll 8
        for (int d = 0; d < 64; d++) {
            ulonglong2 kv = *(const ulonglong2*)&sKT[d * PADK + kk];
            ull q0, q1, q2;
            DUP2(q0, q0p[d]); DUP2(q1, q1p[d]); DUP2(q2, q2p[d]);
            FMA2(a00, q0, kv.x); FMA2(a01, q0, kv.y);
            FMA2(a10, q1, kv.x); FMA2(a11, q1, kv.y);
            FMA2(a20, q2, kv.x); FMA2(a21, q2, kv.y);
        }
    }

    // Phase 2 (registers): per-u softmax over this row's 64 keys.
    // 16-thread group (consecutive lanes) holds the full row.
    float ev[3][4];
    {
        const float sc = 0.125f;
        ull ra[3][2] = {{a00, a01}, {a10, a11}, {a20, a21}};
#pragma unroll
        for (int jj = 0; jj < 3; jj++) {
            float s0 = lo2(ra[jj][0]) * sc, s1 = hi2(ra[jj][0]) * sc;
            float s2 = lo2(ra[jj][1]) * sc, s3 = hi2(ra[jj][1]) * sc;
            float mm = fmaxf(fmaxf(s0, s1), fmaxf(s2, s3));
            mm = fmaxf(mm, __shfl_xor_sync(0xffffffffu, mm, 1));
            mm = fmaxf(mm, __shfl_xor_sync(0xffffffffu, mm, 2));
            mm = fmaxf(mm, __shfl_xor_sync(0xffffffffu, mm, 4));
            mm = fmaxf(mm, __shfl_xor_sync(0xffffffffu, mm, 8));
            float e0 = __expf(s0 - mm), e1 = __expf(s1 - mm);
            float e2 = __expf(s2 - mm), e3 = __expf(s3 - mm);
            float ss = (e0 + e1) + (e2 + e3);
            ss += __shfl_xor_sync(0xffffffffu, ss, 1);
            ss += __shfl_xor_sync(0xffffffffu, ss, 2);
            ss += __shfl_xor_sync(0xffffffffu, ss, 4);
            ss += __shfl_xor_sync(0xffffffffu, ss, 8);
            ev[jj][0] = e0; ev[jj][1] = e1; ev[jj][2] = e2; ev[jj][3] = e3;
            int u = u0 + jj;
            if (kt == 0 && u < U_) {
                g_pm[(bh * NSPLIT + sp) * U_ + u] = mm;
                g_ps[(bh * NSPLIT + sp) * U_ + u] = ss;
            }
        }
    }
    __syncthreads();   // all sQE (Q) reads done -> safe to overwrite with E

#pragma unroll
    for (int jj = 0; jj < 3; jj++)
        *(float4*)(sQE + (u0 + jj) * 64 + kk) =
            make_float4(ev[jj][0], ev[jj][1], ev[jj][2], ev[jj][3]);

    asm volatile("cp.async.wait_group 0;");
    __syncthreads();   // E visible + V arrived

    // Phase 3: AV[u][d] = sum_k E[u][k]*V[k][d]  (3u x 4d per thread)
    {
        int dd = kk;   // same 16x16 decomposition, dt == kt
        ull c00 = 0, c01 = 0, c10 = 0, c11 = 0, c20 = 0, c21 = 0;
        const float* e0p = sQE + (u0 + 0) * 64;
        const float* e1p = sQE + (u0 + 1) * 64;
        const float* e2p = sQE + (u0 + 2) * 64;
#pragma unroll 8
        for (int k = 0; k < 64; k++) {
            ulonglong2 vv = *(const ulonglong2*)&sV[k * PADK + dd];
            ull e0, e1, e2;
            DUP2(e0, e0p[k]); DUP2(e1, e1p[k]); DUP2(e2, e2p[k]);
            FMA2(c00, e0, vv.x); FMA2(c01, e0, vv.y);
            FMA2(c10, e1, vv.x); FMA2(c11, e1, vv.y);
            FMA2(c20, e2, vv.x); FMA2(c21, e2, vv.y);
        }
        float* pa = g_pacc + (size_t)(bh * NSPLIT + sp) * U_ * D_;
        if (u0 + 0 < U_)
            *(float4*)&pa[(u0 + 0) * D_ + dd] =
                make_float4(lo2(c00), hi2(c00), lo2(c01), hi2(c01));
        if (u0 + 1 < U_)
            *(float4*)&pa[(u0 + 1) * D_ + dd] =
                make_float4(lo2(c10), hi2(c10), lo2(c11), hi2(c11));
        if (u0 + 2 < U_)
            *(float4*)&pa[(u0 + 2) * D_ + dd] =
                make_float4(lo2(c20), hi2(c20), lo2(c21), hi2(c21));
    }
}

// ---------------------------------------------------------------------------
// Kernel 6: combine partials. grid = (U_, B*H), 64 threads.
// ---------------------------------------------------------------------------
__global__ void __launch_bounds__(64) kernel_combine(float* __restrict__ out) {
    __shared__ float sw[NSPLIT];
    __shared__ float red[64];
    int u = blockIdx.x;
    int bh = blockIdx.y;
    int h = bh & 7, b = bh >> 3;
    int t = threadIdx.x;

    float m = g_pm[(bh * NSPLIT + t) * U_ + u];
    float s = g_ps[(bh * NSPLIT + t) * U_ + u];
    red[t] = m;
    __syncthreads();
    for (int st = 32; st; st >>= 1) {
        if (t < st) red[t] = fmaxf(red[t], red[t + st]);
        __syncthreads();
    }
    float M = red[0];
    __syncthreads();
    float e = __expf(m - M);
    red[t] = e * s;
    __syncthreads();
    for (int st = 32; st; st >>= 1) {
        if (t < st) red[t] += red[t + st];
        __syncthreads();
    }
    float inv = 1.0f / red[0];
    sw[t] = e * inv;
    __syncthreads();

    float acc = 0.0f;
    const float* pa = g_pacc + (size_t)bh * NSPLIT * U_ * D_ + u * D_ + t;
#pragma unroll 8
    for (int sp = 0; sp < NSPLIT; sp++)
        acc += pa[(size_t)sp * U_ * D_] * sw[sp];
    int lsel = g_Mtop[bh * U_ + u];
    out[((b * L_ + lsel) * H_ + h) * D_ + t] = acc;
}

// ---------------------------------------------------------------------------
extern "C" void kernel_launch(void* const* d_in, const int* in_sizes, int n_in,
                              void* d_out, int out_size) {
    const float* Q = (const float*)d_in[0];
    const float* K = (const float*)d_in[1];
    const float* V = (const float*)d_in[2];
    const int* idx = (const int*)d_in[3];   // int32 (JAX x64 disabled)
    float* out = (float*)d_out;

    cudaFuncSetAttribute((const void*)kernel_M,
                         cudaFuncAttributePreferredSharedMemoryCarveout, 0);
    cudaFuncSetAttribute((const void*)kernel_attn_part,
                         cudaFuncAttributeMaxDynamicSharedMemorySize, SMEM_BYTES);

    // Order: ncu capture slot (position 4) lands on kernel_attn_part.
    kernel_M<<<(B_ * H_ * L_) / 8, 256>>>(Q, K, idx);
    kernel_topk<<<B_ * H_, 256>>>();
    kernel_zero_mean<<<(B_ * H_ * D_ + 255) / 256, 256>>>();
    kernel_attn_part<<<B_ * H_ * NSPLIT, 256, SMEM_BYTES>>>(Q, K, V);
    kernel_mean_part<<<B_ * H_ * 32, 256>>>(V);
    kernel_fill<<<(B_ * L_ * H_ * D_ / 4 + 255) / 256, 256>>>(out);
    kernel_combine<<<dim3(U_, B_ * H_), 64>>>(out);
}